// round 1
// baseline (speedup 1.0000x reference)
#include <cuda_runtime.h>

#define BS   16
#define N1   4096
#define N2   1024
#define C1   128
#define C2   256
#define CH   256
#define COUT 256

// Scratch (static device globals -- no allocation)
__device__ int   g_idx[BS * N1 * 3];
__device__ float g_wts[BS * N1 * 3];
__device__ float g_G2 [BS * N2 * CH];   // fea2 @ W1b      (16 MB)
__device__ float g_H  [BS * N1 * CH];   // hidden layer    (67 MB)

// ---------------------------------------------------------------------------
// 3-NN + inverse-distance weights. One thread per query point; xyz2 in smem.
// ---------------------------------------------------------------------------
__global__ __launch_bounds__(256) void knn_kernel(
    const float* __restrict__ xyz1, const float* __restrict__ xyz2,
    int* __restrict__ idx, float* __restrict__ wts)
{
    __shared__ float sx[N2], sy[N2], sz[N2];
    int b = blockIdx.y;
    const float* x2 = xyz2 + (size_t)b * N2 * 3;
    for (int i = threadIdx.x; i < N2; i += 256) {
        sx[i] = x2[3 * i + 0];
        sy[i] = x2[3 * i + 1];
        sz[i] = x2[3 * i + 2];
    }
    __syncthreads();

    int p = blockIdx.x * 256 + threadIdx.x;
    size_t gp = (size_t)b * N1 + p;
    float px = xyz1[gp * 3 + 0];
    float py = xyz1[gp * 3 + 1];
    float pz = xyz1[gp * 3 + 2];

    float d0 = 3.4e38f, d1 = 3.4e38f, d2 = 3.4e38f;
    int   i0 = 0, i1 = 0, i2 = 0;
    #pragma unroll 4
    for (int j = 0; j < N2; j++) {
        float dx = px - sx[j], dy = py - sy[j], dz = pz - sz[j];
        float d = fmaf(dx, dx, fmaf(dy, dy, dz * dz));
        if (d < d2) {
            if (d < d1) {
                d2 = d1; i2 = i1;
                if (d < d0) { d1 = d0; i1 = i0; d0 = d; i0 = j; }
                else        { d1 = d;  i1 = j; }
            } else { d2 = d; i2 = j; }
        }
    }
    float r0 = 1.0f / (d0 + 1e-8f);
    float r1 = 1.0f / (d1 + 1e-8f);
    float r2 = 1.0f / (d2 + 1e-8f);
    float s  = 1.0f / (r0 + r1 + r2);
    idx[gp * 3 + 0] = i0;  wts[gp * 3 + 0] = r0 * s;
    idx[gp * 3 + 1] = i1;  wts[gp * 3 + 1] = r1 * s;
    idx[gp * 3 + 2] = i2;  wts[gp * 3 + 2] = r2 * s;
}

// ---------------------------------------------------------------------------
// Tiled fp32 SGEMM: C[M,N] = A[M,K] @ B[K,N]  (row-major), BM=BN=128, BK=16,
// 256 threads, 8x8 microtile in 2x2-of-4x4 layout.
// MODE 0: plain store           (G2 = fea2 @ W1b)
// MODE 1: + 3-NN gather from G2, + bias, relu   (hidden layer)
// MODE 2: + bias, relu                          (output layer)
// M,N,K all multiples of tile sizes here -> no bounds checks.
// ---------------------------------------------------------------------------
template <int MODE>
__global__ __launch_bounds__(256) void sgemm_kernel(
    const float* __restrict__ A, const float* __restrict__ B,
    float* __restrict__ C, int M, int N, int K,
    const float* __restrict__ bias,
    const float* __restrict__ G2, const int* __restrict__ idx,
    const float* __restrict__ wts)
{
    __shared__ float As[16][128];
    __shared__ float Bs[16][128];

    int tid = threadIdx.x;
    int tx = tid & 15;          // 0..15 -> col groups
    int ty = tid >> 4;          // 0..15 -> row groups
    int row0 = blockIdx.y * 128;
    int col0 = blockIdx.x * 128;

    float acc[8][8];
    #pragma unroll
    for (int i = 0; i < 8; i++)
        #pragma unroll
        for (int j = 0; j < 8; j++) acc[i][j] = 0.0f;

    const float* Ag = A + (size_t)row0 * K;
    const float* Bg = B + col0;

    for (int k0 = 0; k0 < K; k0 += 16) {
        // Load A tile (128 rows x 16 k), transposed into As[k][m]
        #pragma unroll
        for (int l = 0; l < 2; l++) {
            int f  = tid + l * 256;       // 0..511 float4s
            int r  = f >> 2;              // row in tile
            int kq = (f & 3) * 4;         // k offset
            float4 v = *reinterpret_cast<const float4*>(Ag + (size_t)r * K + k0 + kq);
            As[kq + 0][r] = v.x;
            As[kq + 1][r] = v.y;
            As[kq + 2][r] = v.z;
            As[kq + 3][r] = v.w;
        }
        // Load B tile (16 k x 128 cols), row-major
        #pragma unroll
        for (int l = 0; l < 2; l++) {
            int f  = tid + l * 256;
            int kr = f >> 5;              // 0..15
            int cq = (f & 31) * 4;        // col offset
            *reinterpret_cast<float4*>(&Bs[kr][cq]) =
                *reinterpret_cast<const float4*>(Bg + (size_t)(k0 + kr) * N + cq);
        }
        __syncthreads();

        #pragma unroll
        for (int kk = 0; kk < 16; kk++) {
            float ar[8], br[8];
            float4 t;
            t = *reinterpret_cast<float4*>(&As[kk][ty * 4]);
            ar[0] = t.x; ar[1] = t.y; ar[2] = t.z; ar[3] = t.w;
            t = *reinterpret_cast<float4*>(&As[kk][64 + ty * 4]);
            ar[4] = t.x; ar[5] = t.y; ar[6] = t.z; ar[7] = t.w;
            t = *reinterpret_cast<float4*>(&Bs[kk][tx * 4]);
            br[0] = t.x; br[1] = t.y; br[2] = t.z; br[3] = t.w;
            t = *reinterpret_cast<float4*>(&Bs[kk][64 + tx * 4]);
            br[4] = t.x; br[5] = t.y; br[6] = t.z; br[7] = t.w;
            #pragma unroll
            for (int i = 0; i < 8; i++)
                #pragma unroll
                for (int j = 0; j < 8; j++)
                    acc[i][j] = fmaf(ar[i], br[j], acc[i][j]);
        }
        __syncthreads();
    }

    // ---- Epilogue ----
    int rowIdx[8];
    #pragma unroll
    for (int i = 0; i < 8; i++)
        rowIdx[i] = row0 + ((i < 4) ? (ty * 4 + i) : (64 + ty * 4 + i - 4));

    if (MODE == 1) {
        // += sum_k w_k * G2[batch, idx_k, col]
        #pragma unroll
        for (int i = 0; i < 8; i++) {
            int gr = rowIdx[i];
            int b  = gr >> 12;            // / 4096
            const int*   ip = idx + (size_t)gr * 3;
            const float* wp = wts + (size_t)gr * 3;
            #pragma unroll
            for (int k = 0; k < 3; k++) {
                int   ii = ip[k];
                float wt = wp[k];
                const float* gpr = G2 + ((size_t)((b << 10) + ii) * CH) + col0;
                float4 u0 = *reinterpret_cast<const float4*>(gpr + tx * 4);
                float4 u1 = *reinterpret_cast<const float4*>(gpr + 64 + tx * 4);
                acc[i][0] = fmaf(wt, u0.x, acc[i][0]);
                acc[i][1] = fmaf(wt, u0.y, acc[i][1]);
                acc[i][2] = fmaf(wt, u0.z, acc[i][2]);
                acc[i][3] = fmaf(wt, u0.w, acc[i][3]);
                acc[i][4] = fmaf(wt, u1.x, acc[i][4]);
                acc[i][5] = fmaf(wt, u1.y, acc[i][5]);
                acc[i][6] = fmaf(wt, u1.z, acc[i][6]);
                acc[i][7] = fmaf(wt, u1.w, acc[i][7]);
            }
        }
    }

    if (MODE >= 1) {
        float bi[8];
        float4 v0 = *reinterpret_cast<const float4*>(bias + col0 + tx * 4);
        float4 v1 = *reinterpret_cast<const float4*>(bias + col0 + 64 + tx * 4);
        bi[0] = v0.x; bi[1] = v0.y; bi[2] = v0.z; bi[3] = v0.w;
        bi[4] = v1.x; bi[5] = v1.y; bi[6] = v1.z; bi[7] = v1.w;
        #pragma unroll
        for (int i = 0; i < 8; i++)
            #pragma unroll
            for (int j = 0; j < 8; j++)
                acc[i][j] = fmaxf(acc[i][j] + bi[j], 0.0f);
    }

    #pragma unroll
    for (int i = 0; i < 8; i++) {
        float* cp = C + (size_t)rowIdx[i] * N + col0;
        float4 s0, s1;
        s0.x = acc[i][0]; s0.y = acc[i][1]; s0.z = acc[i][2]; s0.w = acc[i][3];
        s1.x = acc[i][4]; s1.y = acc[i][5]; s1.z = acc[i][6]; s1.w = acc[i][7];
        *reinterpret_cast<float4*>(cp + tx * 4)      = s0;
        *reinterpret_cast<float4*>(cp + 64 + tx * 4) = s1;
    }
}

// ---------------------------------------------------------------------------

extern "C" void kernel_launch(void* const* d_in, const int* in_sizes, int n_in,
                              void* d_out, int out_size)
{
    const float* xyz1 = (const float*)d_in[0];
    const float* xyz2 = (const float*)d_in[1];
    const float* fea1 = (const float*)d_in[2];
    const float* fea2 = (const float*)d_in[3];
    const float* W1   = (const float*)d_in[4];
    const float* b1   = (const float*)d_in[5];
    const float* W2   = (const float*)d_in[6];
    const float* b2   = (const float*)d_in[7];
    float* out = (float*)d_out;

    void *p_idx, *p_wts, *p_G2, *p_H;
    cudaGetSymbolAddress(&p_idx, g_idx);
    cudaGetSymbolAddress(&p_wts, g_wts);
    cudaGetSymbolAddress(&p_G2,  g_G2);
    cudaGetSymbolAddress(&p_H,   g_H);
    int*   idxp = (int*)p_idx;
    float* wtsp = (float*)p_wts;
    float* G2p  = (float*)p_G2;
    float* Hp   = (float*)p_H;

    // 1) 3-NN search + weights
    knn_kernel<<<dim3(N1 / 256, BS), 256>>>(xyz1, xyz2, idxp, wtsp);

    // 2) G2 = fea2 @ W1b   (W1b = rows 128..383 of W1)
    sgemm_kernel<0><<<dim3(CH / 128, (BS * N2) / 128), 256>>>(
        fea2, W1 + (size_t)C1 * CH, G2p, BS * N2, CH, C2,
        nullptr, nullptr, nullptr, nullptr);

    // 3) H = relu(fea1 @ W1a + gather(G2) + b1)
    sgemm_kernel<1><<<dim3(CH / 128, (BS * N1) / 128), 256>>>(
        fea1, W1, Hp, BS * N1, CH, C1,
        b1, G2p, idxp, wtsp);

    // 4) out = relu(H @ W2 + b2)
    sgemm_kernel<2><<<dim3(COUT / 128, (BS * N1) / 128), 256>>>(
        Hp, W2, out, BS * N1, COUT, CH,
        b2, nullptr, nullptr, nullptr);
}

// round 2
// speedup vs baseline: 1.6925x; 1.6925x over previous
#include <cuda_runtime.h>
#include <cstdint>

#define BS   16
#define N1   4096
#define N2   1024
#define C1   128
#define C2   256
#define CH   256
#define COUT 256

// Scratch (static device globals -- no allocation)
__device__ int   g_idx[BS * N1 * 3];
__device__ float g_wts[BS * N1 * 3];
__device__ float g_G2 [BS * N2 * CH];   // fea2 @ W1b      (16 MB)
__device__ float g_H  [BS * N1 * CH];   // hidden layer    (67 MB)

// ---------------------------------------------------------------------------
// 3-NN + inverse-distance weights. One thread per query point; xyz2 in smem.
// ---------------------------------------------------------------------------
__global__ __launch_bounds__(256) void knn_kernel(
    const float* __restrict__ xyz1, const float* __restrict__ xyz2,
    int* __restrict__ idx, float* __restrict__ wts)
{
    __shared__ float sx[N2], sy[N2], sz[N2];
    int b = blockIdx.y;
    const float* x2 = xyz2 + (size_t)b * N2 * 3;
    for (int i = threadIdx.x; i < N2; i += 256) {
        sx[i] = x2[3 * i + 0];
        sy[i] = x2[3 * i + 1];
        sz[i] = x2[3 * i + 2];
    }
    __syncthreads();

    int p = blockIdx.x * 256 + threadIdx.x;
    size_t gp = (size_t)b * N1 + p;
    float px = xyz1[gp * 3 + 0];
    float py = xyz1[gp * 3 + 1];
    float pz = xyz1[gp * 3 + 2];

    float d0 = 3.4e38f, d1 = 3.4e38f, d2 = 3.4e38f;
    int   i0 = 0, i1 = 0, i2 = 0;
    #pragma unroll 4
    for (int j = 0; j < N2; j++) {
        float dx = px - sx[j], dy = py - sy[j], dz = pz - sz[j];
        float d = fmaf(dx, dx, fmaf(dy, dy, dz * dz));
        if (d < d2) {
            if (d < d1) {
                d2 = d1; i2 = i1;
                if (d < d0) { d1 = d0; i1 = i0; d0 = d; i0 = j; }
                else        { d1 = d;  i1 = j; }
            } else { d2 = d; i2 = j; }
        }
    }
    float r0 = 1.0f / (d0 + 1e-8f);
    float r1 = 1.0f / (d1 + 1e-8f);
    float r2 = 1.0f / (d2 + 1e-8f);
    float s  = 1.0f / (r0 + r1 + r2);
    idx[gp * 3 + 0] = i0;  wts[gp * 3 + 0] = r0 * s;
    idx[gp * 3 + 1] = i1;  wts[gp * 3 + 1] = r1 * s;
    idx[gp * 3 + 2] = i2;  wts[gp * 3 + 2] = r2 * s;
}

// ---------------------------------------------------------------------------
// TF32 tensor-core GEMM: C[M,N] = A[M,K] @ B[K,N]  (row-major, fp32 in/out)
// Tile 128x128, BK=32, 256 threads = 8 warps (4 M x 2 N), warp tile 32x64,
// built from mma.sync.m16n8k8.tf32 atoms (2 m-atoms x 8 n-atoms per warp).
// MODE 0: plain store           (G2 = fea2 @ W1b)
// MODE 1: + 3-NN gather from G2, + bias, relu   (hidden layer)
// MODE 2: + bias, relu                          (output layer)
// All dims are multiples of the tile sizes -> no bounds checks.
// ---------------------------------------------------------------------------

__device__ __forceinline__ uint32_t f2tf(float f) {
    uint32_t r;
    asm("cvt.rna.tf32.f32 %0, %1;" : "=r"(r) : "f"(f));
    return r;
}

__device__ __forceinline__ void mma_tf32(float c[4], const uint32_t a[4],
                                         const uint32_t b[2]) {
    asm volatile(
        "mma.sync.aligned.m16n8k8.row.col.f32.tf32.tf32.f32 "
        "{%0,%1,%2,%3}, {%4,%5,%6,%7}, {%8,%9}, {%0,%1,%2,%3};\n"
        : "+f"(c[0]), "+f"(c[1]), "+f"(c[2]), "+f"(c[3])
        : "r"(a[0]), "r"(a[1]), "r"(a[2]), "r"(a[3]), "r"(b[0]), "r"(b[1]));
}

template <int MODE>
__global__ __launch_bounds__(256, 2) void tgemm_kernel(
    const float* __restrict__ A, const float* __restrict__ B,
    float* __restrict__ C, int M, int N, int K,
    const float* __restrict__ bias,
    const float* __restrict__ G2, const int* __restrict__ idx,
    const float* __restrict__ wts)
{
    __shared__ uint32_t As[32][132];   // [k][m], +4 pad
    __shared__ uint32_t Bs[32][132];   // [k][n], +4 pad

    int tid  = threadIdx.x;
    int lane = tid & 31;
    int w    = tid >> 5;
    int gid  = lane >> 2;      // 0..7
    int tig  = lane & 3;       // 0..3
    int mw   = (w >> 1) * 32;  // warp m offset (4 rows of warps)
    int nw   = (w & 1) * 64;   // warp n offset (2 cols of warps)
    int row0 = blockIdx.y * 128;
    int col0 = blockIdx.x * 128;

    float acc[2][8][4];
    #pragma unroll
    for (int ma = 0; ma < 2; ma++)
        #pragma unroll
        for (int nb = 0; nb < 8; nb++)
            #pragma unroll
            for (int q = 0; q < 4; q++) acc[ma][nb][q] = 0.0f;

    const float* Ag = A + (size_t)row0 * K;
    const float* Bg = B + col0;

    for (int k0 = 0; k0 < K; k0 += 32) {
        // A tile: 128 rows x 32 k, store transposed As[k][m] with tf32 convert
        #pragma unroll
        for (int l = 0; l < 4; l++) {
            int f  = tid + l * 256;      // 0..1023 float4s
            int r  = f >> 3;             // row 0..127
            int kq = (f & 7) * 4;        // k offset 0..28
            float4 v = *reinterpret_cast<const float4*>(Ag + (size_t)r * K + k0 + kq);
            As[kq + 0][r] = f2tf(v.x);
            As[kq + 1][r] = f2tf(v.y);
            As[kq + 2][r] = f2tf(v.z);
            As[kq + 3][r] = f2tf(v.w);
        }
        // B tile: 32 k x 128 cols, row-major, vectorized store
        #pragma unroll
        for (int l = 0; l < 4; l++) {
            int f  = tid + l * 256;
            int r  = f >> 5;             // k row 0..31
            int cq = (f & 31) * 4;       // col 0..124
            float4 v = *reinterpret_cast<const float4*>(Bg + (size_t)(k0 + r) * N + cq);
            uint4 u;
            u.x = f2tf(v.x); u.y = f2tf(v.y); u.z = f2tf(v.z); u.w = f2tf(v.w);
            *reinterpret_cast<uint4*>(&Bs[r][cq]) = u;
        }
        __syncthreads();

        #pragma unroll
        for (int kk = 0; kk < 32; kk += 8) {
            uint32_t a[2][4], b[8][2];
            #pragma unroll
            for (int ma = 0; ma < 2; ma++) {
                int mb = mw + ma * 16;
                a[ma][0] = As[kk + tig    ][mb + gid    ];
                a[ma][1] = As[kk + tig    ][mb + gid + 8];
                a[ma][2] = As[kk + tig + 4][mb + gid    ];
                a[ma][3] = As[kk + tig + 4][mb + gid + 8];
            }
            #pragma unroll
            for (int nb = 0; nb < 8; nb++) {
                int cc = nw + nb * 8 + gid;
                b[nb][0] = Bs[kk + tig    ][cc];
                b[nb][1] = Bs[kk + tig + 4][cc];
            }
            #pragma unroll
            for (int ma = 0; ma < 2; ma++)
                #pragma unroll
                for (int nb = 0; nb < 8; nb++)
                    mma_tf32(acc[ma][nb], a[ma], b[nb]);
        }
        __syncthreads();
    }

    // ---- Epilogue ----
    // Thread owns rows: (mw+ma*16+gid) and (+8); cols: nw+nb*8+2*tig (+1)
    int colb[8];
    #pragma unroll
    for (int nb = 0; nb < 8; nb++) colb[nb] = col0 + nw + nb * 8 + 2 * tig;

    if (MODE == 1) {
        #pragma unroll
        for (int ma = 0; ma < 2; ma++) {
            #pragma unroll
            for (int h = 0; h < 2; h++) {        // h=0 -> c0/c1 rows, h=1 -> c2/c3
                int gr = row0 + mw + ma * 16 + gid + h * 8;
                int bb = gr >> 12;               // / 4096
                const int*   ip = idx + (size_t)gr * 3;
                const float* wp = wts + (size_t)gr * 3;
                #pragma unroll
                for (int k = 0; k < 3; k++) {
                    int   ii = ip[k];
                    float wt = wp[k];
                    const float* gpr = G2 + (size_t)((bb << 10) + ii) * CH;
                    #pragma unroll
                    for (int nb = 0; nb < 8; nb++) {
                        float2 u = *reinterpret_cast<const float2*>(gpr + colb[nb]);
                        acc[ma][nb][2 * h + 0] = fmaf(wt, u.x, acc[ma][nb][2 * h + 0]);
                        acc[ma][nb][2 * h + 1] = fmaf(wt, u.y, acc[ma][nb][2 * h + 1]);
                    }
                }
            }
        }
    }

    if (MODE >= 1) {
        #pragma unroll
        for (int nb = 0; nb < 8; nb++) {
            float2 bv = *reinterpret_cast<const float2*>(bias + colb[nb]);
            #pragma unroll
            for (int ma = 0; ma < 2; ma++) {
                acc[ma][nb][0] = fmaxf(acc[ma][nb][0] + bv.x, 0.0f);
                acc[ma][nb][1] = fmaxf(acc[ma][nb][1] + bv.y, 0.0f);
                acc[ma][nb][2] = fmaxf(acc[ma][nb][2] + bv.x, 0.0f);
                acc[ma][nb][3] = fmaxf(acc[ma][nb][3] + bv.y, 0.0f);
            }
        }
    }

    #pragma unroll
    for (int ma = 0; ma < 2; ma++) {
        int rlo = row0 + mw + ma * 16 + gid;
        int rhi = rlo + 8;
        #pragma unroll
        for (int nb = 0; nb < 8; nb++) {
            float2 s0, s1;
            s0.x = acc[ma][nb][0]; s0.y = acc[ma][nb][1];
            s1.x = acc[ma][nb][2]; s1.y = acc[ma][nb][3];
            *reinterpret_cast<float2*>(C + (size_t)rlo * N + colb[nb]) = s0;
            *reinterpret_cast<float2*>(C + (size_t)rhi * N + colb[nb]) = s1;
        }
    }
}

// ---------------------------------------------------------------------------

extern "C" void kernel_launch(void* const* d_in, const int* in_sizes, int n_in,
                              void* d_out, int out_size)
{
    const float* xyz1 = (const float*)d_in[0];
    const float* xyz2 = (const float*)d_in[1];
    const float* fea1 = (const float*)d_in[2];
    const float* fea2 = (const float*)d_in[3];
    const float* W1   = (const float*)d_in[4];
    const float* b1   = (const float*)d_in[5];
    const float* W2   = (const float*)d_in[6];
    const float* b2   = (const float*)d_in[7];
    float* out = (float*)d_out;

    void *p_idx, *p_wts, *p_G2, *p_H;
    cudaGetSymbolAddress(&p_idx, g_idx);
    cudaGetSymbolAddress(&p_wts, g_wts);
    cudaGetSymbolAddress(&p_G2,  g_G2);
    cudaGetSymbolAddress(&p_H,   g_H);
    int*   idxp = (int*)p_idx;
    float* wtsp = (float*)p_wts;
    float* G2p  = (float*)p_G2;
    float* Hp   = (float*)p_H;

    // 1) 3-NN search + weights
    knn_kernel<<<dim3(N1 / 256, BS), 256>>>(xyz1, xyz2, idxp, wtsp);

    // 2) G2 = fea2 @ W1b   (W1b = rows 128..383 of W1)
    tgemm_kernel<0><<<dim3(CH / 128, (BS * N2) / 128), 256>>>(
        fea2, W1 + (size_t)C1 * CH, G2p, BS * N2, CH, C2,
        nullptr, nullptr, nullptr, nullptr);

    // 3) H = relu(fea1 @ W1a + gather(G2) + b1)
    tgemm_kernel<1><<<dim3(CH / 128, (BS * N1) / 128), 256>>>(
        fea1, W1, Hp, BS * N1, CH, C1,
        b1, G2p, idxp, wtsp);

    // 4) out = relu(H @ W2 + b2)
    tgemm_kernel<2><<<dim3(COUT / 128, (BS * N1) / 128), 256>>>(
        Hp, W2, out, BS * N1, COUT, CH,
        b2, nullptr, nullptr, nullptr);
}

// round 4
// speedup vs baseline: 2.5251x; 1.4919x over previous
#include <cuda_runtime.h>
#include <cuda_fp16.h>
#include <cstdint>

#define BS   16
#define N1   4096
#define N2   1024
#define C1   128
#define C2   256
#define CH   256
#define COUT 256

// Scratch (static device globals -- no allocation)
__device__ int    g_idx[BS * N1 * 3];
__device__ float  g_wts[BS * N1 * 3];
__device__ float  g_G2 [BS * N2 * CH];     // fea2 @ W1b  (fp32, 16 MB)
__device__ __half g_Hh [BS * N1 * CH];     // hidden layer (fp16, 33 MB)
__device__ __half g_Wt1[CH * (C1 + C2)];   // W1^T [256][384] fp16
__device__ __half g_Wt2[COUT * CH];        // W2^T [256][256] fp16

// ---------------------------------------------------------------------------
__device__ __forceinline__ uint32_t smem_u32(const void* p) {
    uint32_t a;
    asm("{ .reg .u64 t; cvta.to.shared.u64 t, %1; cvt.u32.u64 %0, t; }"
        : "=r"(a) : "l"(p));
    return a;
}

__device__ __forceinline__ void ldm_x4(uint32_t r[4], uint32_t addr) {
    asm volatile("ldmatrix.sync.aligned.m8n8.x4.shared.b16 {%0,%1,%2,%3}, [%4];"
                 : "=r"(r[0]), "=r"(r[1]), "=r"(r[2]), "=r"(r[3]) : "r"(addr));
}

__device__ __forceinline__ void mma_f16(float c[4], const uint32_t a[4],
                                        const uint32_t b[2]) {
    asm volatile(
        "mma.sync.aligned.m16n8k16.row.col.f32.f16.f16.f32 "
        "{%0,%1,%2,%3}, {%4,%5,%6,%7}, {%8,%9}, {%0,%1,%2,%3};\n"
        : "+f"(c[0]), "+f"(c[1]), "+f"(c[2]), "+f"(c[3])
        : "r"(a[0]), "r"(a[1]), "r"(a[2]), "r"(a[3]), "r"(b[0]), "r"(b[1]));
}

// ---------------------------------------------------------------------------
// 3-NN + inverse-distance weights
// ---------------------------------------------------------------------------
__global__ __launch_bounds__(256) void knn_kernel(
    const float* __restrict__ xyz1, const float* __restrict__ xyz2,
    int* __restrict__ idx, float* __restrict__ wts)
{
    __shared__ float sx[N2], sy[N2], sz[N2];
    int b = blockIdx.y;
    const float* x2 = xyz2 + (size_t)b * N2 * 3;
    for (int i = threadIdx.x; i < N2; i += 256) {
        sx[i] = x2[3 * i + 0];
        sy[i] = x2[3 * i + 1];
        sz[i] = x2[3 * i + 2];
    }
    __syncthreads();

    int p = blockIdx.x * 256 + threadIdx.x;
    size_t gp = (size_t)b * N1 + p;
    float px = xyz1[gp * 3 + 0];
    float py = xyz1[gp * 3 + 1];
    float pz = xyz1[gp * 3 + 2];

    float d0 = 3.4e38f, d1 = 3.4e38f, d2 = 3.4e38f;
    int   i0 = 0, i1 = 0, i2 = 0;
    #pragma unroll 4
    for (int j = 0; j < N2; j++) {
        float dx = px - sx[j], dy = py - sy[j], dz = pz - sz[j];
        float d = fmaf(dx, dx, fmaf(dy, dy, dz * dz));
        if (d < d2) {
            if (d < d1) {
                d2 = d1; i2 = i1;
                if (d < d0) { d1 = d0; i1 = i0; d0 = d; i0 = j; }
                else        { d1 = d;  i1 = j; }
            } else { d2 = d; i2 = j; }
        }
    }
    float r0 = 1.0f / (d0 + 1e-8f);
    float r1 = 1.0f / (d1 + 1e-8f);
    float r2 = 1.0f / (d2 + 1e-8f);
    float s  = 1.0f / (r0 + r1 + r2);
    idx[gp * 3 + 0] = i0;  wts[gp * 3 + 0] = r0 * s;
    idx[gp * 3 + 1] = i1;  wts[gp * 3 + 1] = r1 * s;
    idx[gp * 3 + 2] = i2;  wts[gp * 3 + 2] = r2 * s;
}

// Weight transpose + fp16 convert: Wt[n*K + k] = (half)W[k*256 + n]
__global__ __launch_bounds__(256) void transpose_w(
    const float* __restrict__ W, __half* __restrict__ Wt, int K)
{
    int i = blockIdx.x * 256 + threadIdx.x;
    if (i < K * 256) {
        int k = i >> 8, n = i & 255;
        Wt[n * K + k] = __float2half_rn(W[i]);
    }
}

// ---------------------------------------------------------------------------
// fp16 tensor-core GEMM (mma.sync m16n8k16, ldmatrix fragments, fp32 accum)
// CTA tile 128x128, BK=64, 8 warps (2 m x 4 n), warp tile 64x32.
// SW128 swizzle on 128-byte (64-half) smem rows; double-buffered.
// blockIdx.x = n-tile (0..1), blockIdx.y = m-tile (A tile L2 reuse).
// MODE 0: store fp32 C               (G2 = fea2 @ W1b)
// MODE 1: + gather(G2)+bias+relu, store fp16 H
// MODE 2: + bias+relu, store fp32 out
// ---------------------------------------------------------------------------
#define SMEM_BYTES 65536
#define SWZ(off, r) ((off) ^ (((r) & 7) << 4))

template <int MODE, bool AHALF>
__global__ __launch_bounds__(256, 2) void hgemm(
    const void* __restrict__ Avoid, int lda,
    const __half* __restrict__ Bt, int ldb, int K,
    float* __restrict__ Cf, __half* __restrict__ Ch,
    const float* __restrict__ bias,
    const float* __restrict__ G2, const int* __restrict__ idx,
    const float* __restrict__ wts)
{
    extern __shared__ __align__(1024) char smem[];
    const int tid  = threadIdx.x;
    const int lane = tid & 31, w = tid >> 5;
    const int wm   = (w >> 2) * 64;     // warp m offset
    const int wn   = (w & 3) * 32;      // warp n offset
    const int quad = lane >> 2, tq = lane & 3;
    const int row0 = blockIdx.y * 128;
    const int col0 = blockIdx.x * 128;

    float acc[4][4][4];
    #pragma unroll
    for (int ma = 0; ma < 4; ma++)
        #pragma unroll
        for (int na = 0; na < 4; na++)
            #pragma unroll
            for (int q = 0; q < 4; q++) acc[ma][na][q] = 0.0f;

    // --- tile fill lambdas ---
    auto fillA = [&](int k0, char* dst) {
        if (AHALF) {
            const __half* A16 = (const __half*)Avoid;
            #pragma unroll
            for (int l = 0; l < 4; l++) {
                int f = tid + l * 256;
                int r = f >> 3, c8 = (f & 7) << 3;          // 8 halfs
                uint4 v = *reinterpret_cast<const uint4*>(
                    A16 + (size_t)(row0 + r) * lda + k0 + c8);
                *reinterpret_cast<uint4*>(dst + SWZ(r * 128 + c8 * 2, r)) = v;
            }
        } else {
            const float* A32 = (const float*)Avoid;
            #pragma unroll
            for (int l = 0; l < 8; l++) {
                int f = tid + l * 256;
                int r = f >> 4, c4 = (f & 15) << 2;         // 4 floats
                float4 v = *reinterpret_cast<const float4*>(
                    A32 + (size_t)(row0 + r) * lda + k0 + c4);
                __half2 h0 = __floats2half2_rn(v.x, v.y);
                __half2 h1 = __floats2half2_rn(v.z, v.w);
                uint2 u;
                u.x = *reinterpret_cast<uint32_t*>(&h0);
                u.y = *reinterpret_cast<uint32_t*>(&h1);
                *reinterpret_cast<uint2*>(dst + SWZ(r * 128 + c4 * 2, r)) = u;
            }
        }
    };
    auto fillB = [&](int k0, char* dst) {
        #pragma unroll
        for (int l = 0; l < 4; l++) {
            int f = tid + l * 256;
            int r = f >> 3, c8 = (f & 7) << 3;
            uint4 v = *reinterpret_cast<const uint4*>(
                Bt + (size_t)(col0 + r) * ldb + k0 + c8);
            *reinterpret_cast<uint4*>(dst + SWZ(r * 128 + c8 * 2, r)) = v;
        }
    };

    // ldmatrix lane-address components (constant across kk)
    const int t8 = lane >> 3;          // tile index 0..3
    const int rr = lane & 7;
    const int a_row_l = (t8 & 1) * 8 + rr;       // within 16-row atom
    const int a_k8_l  = (t8 >> 1) * 8;
    const int b_n_l   = (t8 >> 1) * 8 + rr;      // within 16-col pair
    const int b_k8_l  = (t8 & 1) * 8;

    int nsteps = K >> 6;
    fillA(0, smem);
    fillB(0, smem + 16384);

    for (int i = 0; i < nsteps; i++) {
        __syncthreads();
        if (i + 1 < nsteps) {
            char* nb = smem + ((i + 1) & 1) * 32768;
            fillA((i + 1) << 6, nb);
            fillB((i + 1) << 6, nb + 16384);
        }
        uint32_t smA = smem_u32(smem + (i & 1) * 32768);
        uint32_t smB = smA + 16384;

        #pragma unroll
        for (int kk = 0; kk < 64; kk += 16) {
            uint32_t a[4][4], b[4][2];
            #pragma unroll
            for (int ma = 0; ma < 4; ma++) {
                int row = wm + ma * 16 + a_row_l;
                int kb  = (kk + a_k8_l) * 2;
                ldm_x4(a[ma], smA + SWZ(row * 128 + kb, row));
            }
            #pragma unroll
            for (int p = 0; p < 2; p++) {
                int n  = wn + p * 16 + b_n_l;
                int kb = (kk + b_k8_l) * 2;
                uint32_t r4[4];
                ldm_x4(r4, smB + SWZ(n * 128 + kb, n));
                b[p * 2 + 0][0] = r4[0]; b[p * 2 + 0][1] = r4[1];
                b[p * 2 + 1][0] = r4[2]; b[p * 2 + 1][1] = r4[3];
            }
            #pragma unroll
            for (int ma = 0; ma < 4; ma++)
                #pragma unroll
                for (int na = 0; na < 4; na++)
                    mma_f16(acc[ma][na], a[ma], b[na]);
        }
    }

    // ---- Epilogue ----
    int colb[4];
    #pragma unroll
    for (int na = 0; na < 4; na++) colb[na] = col0 + wn + na * 8 + 2 * tq;

    if (MODE == 1) {
        #pragma unroll
        for (int ma = 0; ma < 4; ma++) {
            #pragma unroll
            for (int h = 0; h < 2; h++) {
                int gr = row0 + wm + ma * 16 + quad + h * 8;
                int bb = gr >> 12;
                const int*   ip = idx + (size_t)gr * 3;
                const float* wp = wts + (size_t)gr * 3;
                #pragma unroll
                for (int k = 0; k < 3; k++) {
                    int   ii = ip[k];
                    float wt = wp[k];
                    const float* g = G2 + (size_t)((bb << 10) + ii) * CH;
                    #pragma unroll
                    for (int na = 0; na < 4; na++) {
                        float2 u = *reinterpret_cast<const float2*>(g + colb[na]);
                        acc[ma][na][2 * h + 0] = fmaf(wt, u.x, acc[ma][na][2 * h + 0]);
                        acc[ma][na][2 * h + 1] = fmaf(wt, u.y, acc[ma][na][2 * h + 1]);
                    }
                }
            }
        }
    }

    if (MODE >= 1) {
        #pragma unroll
        for (int na = 0; na < 4; na++) {
            float2 bv = *reinterpret_cast<const float2*>(bias + colb[na]);
            #pragma unroll
            for (int ma = 0; ma < 4; ma++) {
                acc[ma][na][0] = fmaxf(acc[ma][na][0] + bv.x, 0.0f);
                acc[ma][na][1] = fmaxf(acc[ma][na][1] + bv.y, 0.0f);
                acc[ma][na][2] = fmaxf(acc[ma][na][2] + bv.x, 0.0f);
                acc[ma][na][3] = fmaxf(acc[ma][na][3] + bv.y, 0.0f);
            }
        }
    }

    #pragma unroll
    for (int ma = 0; ma < 4; ma++) {
        int rlo = row0 + wm + ma * 16 + quad;
        int rhi = rlo + 8;
        #pragma unroll
        for (int na = 0; na < 4; na++) {
            if (MODE == 1) {
                __half2 s0 = __floats2half2_rn(acc[ma][na][0], acc[ma][na][1]);
                __half2 s1 = __floats2half2_rn(acc[ma][na][2], acc[ma][na][3]);
                *reinterpret_cast<__half2*>(Ch + (size_t)rlo * 256 + colb[na]) = s0;
                *reinterpret_cast<__half2*>(Ch + (size_t)rhi * 256 + colb[na]) = s1;
            } else {
                float2 s0, s1;
                s0.x = acc[ma][na][0]; s0.y = acc[ma][na][1];
                s1.x = acc[ma][na][2]; s1.y = acc[ma][na][3];
                *reinterpret_cast<float2*>(Cf + (size_t)rlo * 256 + colb[na]) = s0;
                *reinterpret_cast<float2*>(Cf + (size_t)rhi * 256 + colb[na]) = s1;
            }
        }
    }
}

// ---------------------------------------------------------------------------

extern "C" void kernel_launch(void* const* d_in, const int* in_sizes, int n_in,
                              void* d_out, int out_size)
{
    const float* xyz1 = (const float*)d_in[0];
    const float* xyz2 = (const float*)d_in[1];
    const float* fea1 = (const float*)d_in[2];
    const float* fea2 = (const float*)d_in[3];
    const float* W1   = (const float*)d_in[4];
    const float* b1   = (const float*)d_in[5];
    const float* W2   = (const float*)d_in[6];
    const float* b2   = (const float*)d_in[7];
    float* out = (float*)d_out;

    void *p_idx, *p_wts, *p_G2, *p_Hh, *p_Wt1, *p_Wt2;
    cudaGetSymbolAddress(&p_idx, g_idx);
    cudaGetSymbolAddress(&p_wts, g_wts);
    cudaGetSymbolAddress(&p_G2,  g_G2);
    cudaGetSymbolAddress(&p_Hh,  g_Hh);
    cudaGetSymbolAddress(&p_Wt1, g_Wt1);
    cudaGetSymbolAddress(&p_Wt2, g_Wt2);
    int*    idxp = (int*)p_idx;
    float*  wtsp = (float*)p_wts;
    float*  G2p  = (float*)p_G2;
    __half* Hp   = (__half*)p_Hh;
    __half* Wt1p = (__half*)p_Wt1;
    __half* Wt2p = (__half*)p_Wt2;

    cudaFuncSetAttribute(hgemm<0, false>, cudaFuncAttributeMaxDynamicSharedMemorySize, SMEM_BYTES);
    cudaFuncSetAttribute(hgemm<1, false>, cudaFuncAttributeMaxDynamicSharedMemorySize, SMEM_BYTES);
    cudaFuncSetAttribute(hgemm<2, true >, cudaFuncAttributeMaxDynamicSharedMemorySize, SMEM_BYTES);

    // 0) transpose + fp16-convert weights (tiny)
    transpose_w<<<(384 * 256 + 255) / 256, 256>>>(W1, Wt1p, 384);
    transpose_w<<<(256 * 256 + 255) / 256, 256>>>(W2, Wt2p, 256);

    // 1) 3-NN search + weights
    knn_kernel<<<dim3(N1 / 256, BS), 256>>>(xyz1, xyz2, idxp, wtsp);

    // 2) G2 = fea2 @ W1b   (Wt1 k-offset 128, ldb=384), fp32 out
    hgemm<0, false><<<dim3(2, (BS * N2) / 128), 256, SMEM_BYTES>>>(
        fea2, C2, Wt1p + 128, 384, C2,
        G2p, nullptr, nullptr, nullptr, nullptr, nullptr);

    // 3) H = relu(fea1 @ W1a + gather(G2) + b1), fp16 out
    hgemm<1, false><<<dim3(2, (BS * N1) / 128), 256, SMEM_BYTES>>>(
        fea1, C1, Wt1p, 384, C1,
        nullptr, Hp, b1, G2p, idxp, wtsp);

    // 4) out = relu(H @ W2 + b2), fp32 out
    hgemm<2, true><<<dim3(2, (BS * N1) / 128), 256, SMEM_BYTES>>>(
        Hp, CH, Wt2p, 256, CH,
        out, nullptr, b2, nullptr, nullptr, nullptr);
}

// round 5
// speedup vs baseline: 2.6491x; 1.0491x over previous
#include <cuda_runtime.h>
#include <cuda_fp16.h>
#include <cstdint>

#define BS   16
#define N1   4096
#define N2   1024
#define C1   128
#define C2   256
#define CH   256
#define COUT 256

// Scratch (static device globals -- no allocation)
__device__ int    g_idx[BS * N1 * 3];
__device__ float  g_wts[BS * N1 * 3];
__device__ float  g_G2 [BS * N2 * CH];                 // fea2 @ W1b (fp32)
__device__ __align__(16) __half g_Wt1[CH * (C1 + C2)]; // W1^T [256][384] fp16
__device__ __align__(16) __half g_Wt2[COUT * CH];      // W2^T [256][256] fp16

// ---------------------------------------------------------------------------
__device__ __forceinline__ uint32_t smem_u32(const void* p) {
    uint32_t a;
    asm("{ .reg .u64 t; cvta.to.shared.u64 t, %1; cvt.u32.u64 %0, t; }"
        : "=r"(a) : "l"(p));
    return a;
}
__device__ __forceinline__ void ldm_x4(uint32_t r[4], uint32_t addr) {
    asm volatile("ldmatrix.sync.aligned.m8n8.x4.shared.b16 {%0,%1,%2,%3}, [%4];"
                 : "=r"(r[0]), "=r"(r[1]), "=r"(r[2]), "=r"(r[3]) : "r"(addr));
}
__device__ __forceinline__ void mma_f16(float c[4], const uint32_t a[4],
                                        const uint32_t b[2]) {
    asm volatile(
        "mma.sync.aligned.m16n8k16.row.col.f32.f16.f16.f32 "
        "{%0,%1,%2,%3}, {%4,%5,%6,%7}, {%8,%9}, {%0,%1,%2,%3};\n"
        : "+f"(c[0]), "+f"(c[1]), "+f"(c[2]), "+f"(c[3])
        : "r"(a[0]), "r"(a[1]), "r"(a[2]), "r"(a[3]), "r"(b[0]), "r"(b[1]));
}
#define CP16(dst, src) \
    asm volatile("cp.async.cg.shared.global [%0], [%1], 16;" :: "r"(dst), "l"(src))
#define CP_COMMIT() asm volatile("cp.async.commit_group;" ::: "memory")
#define CP_WAIT0()  asm volatile("cp.async.wait_group 0;" ::: "memory")
#define SWZ(off, r) ((off) ^ (((r) & 7) << 4))

// ---------------------------------------------------------------------------
// 3-NN + inverse-distance weights
// ---------------------------------------------------------------------------
__global__ __launch_bounds__(256) void knn_kernel(
    const float* __restrict__ xyz1, const float* __restrict__ xyz2,
    int* __restrict__ idx, float* __restrict__ wts)
{
    __shared__ float sx[N2], sy[N2], sz[N2];
    int b = blockIdx.y;
    const float* x2 = xyz2 + (size_t)b * N2 * 3;
    for (int i = threadIdx.x; i < N2; i += 256) {
        sx[i] = x2[3 * i + 0];
        sy[i] = x2[3 * i + 1];
        sz[i] = x2[3 * i + 2];
    }
    __syncthreads();

    int p = blockIdx.x * 256 + threadIdx.x;
    size_t gp = (size_t)b * N1 + p;
    float px = xyz1[gp * 3 + 0];
    float py = xyz1[gp * 3 + 1];
    float pz = xyz1[gp * 3 + 2];

    float d0 = 3.4e38f, d1 = 3.4e38f, d2 = 3.4e38f;
    int   i0 = 0, i1 = 0, i2 = 0;
    #pragma unroll 4
    for (int j = 0; j < N2; j++) {
        float dx = px - sx[j], dy = py - sy[j], dz = pz - sz[j];
        float d = fmaf(dx, dx, fmaf(dy, dy, dz * dz));
        if (d < d2) {
            if (d < d1) {
                d2 = d1; i2 = i1;
                if (d < d0) { d1 = d0; i1 = i0; d0 = d; i0 = j; }
                else        { d1 = d;  i1 = j; }
            } else { d2 = d; i2 = j; }
        }
    }
    float r0 = 1.0f / (d0 + 1e-8f);
    float r1 = 1.0f / (d1 + 1e-8f);
    float r2 = 1.0f / (d2 + 1e-8f);
    float s  = 1.0f / (r0 + r1 + r2);
    idx[gp * 3 + 0] = i0;  wts[gp * 3 + 0] = r0 * s;
    idx[gp * 3 + 1] = i1;  wts[gp * 3 + 1] = r1 * s;
    idx[gp * 3 + 2] = i2;  wts[gp * 3 + 2] = r2 * s;
}

// Weight transpose + fp16 convert: Wt[n*K + k] = (half)W[k*256 + n]
__global__ __launch_bounds__(256) void transpose_w(
    const float* __restrict__ W, __half* __restrict__ Wt, int K)
{
    int i = blockIdx.x * 256 + threadIdx.x;
    if (i < K * 256) {
        int k = i >> 8, n = i & 255;
        Wt[n * K + k] = __float2half_rn(W[i]);
    }
}

// ---------------------------------------------------------------------------
// G2 = fea2 @ W1b : fp16 mma GEMM, CTA 128x128, BK=64 (R4-proven structure)
// ---------------------------------------------------------------------------
#define G2_SMEM 65536
__global__ __launch_bounds__(256, 2) void g2_gemm(
    const float* __restrict__ A, const __half* __restrict__ Bt,
    float* __restrict__ Cf)
{
    extern __shared__ __align__(1024) char smem[];
    const int tid  = threadIdx.x;
    const int lane = tid & 31, w = tid >> 5;
    const int wm   = (w >> 2) * 64;
    const int wn   = (w & 3) * 32;
    const int quad = lane >> 2, tq = lane & 3;
    const int row0 = blockIdx.y * 128;
    const int col0 = blockIdx.x * 128;

    float acc[4][4][4];
    #pragma unroll
    for (int ma = 0; ma < 4; ma++)
        #pragma unroll
        for (int na = 0; na < 4; na++)
            #pragma unroll
            for (int q = 0; q < 4; q++) acc[ma][na][q] = 0.0f;

    auto fillA = [&](int k0, char* dst) {
        #pragma unroll
        for (int l = 0; l < 8; l++) {
            int f = tid + l * 256;
            int r = f >> 4, c4 = (f & 15) << 2;
            float4 v = *reinterpret_cast<const float4*>(
                A + (size_t)(row0 + r) * C2 + k0 + c4);
            __half2 h0 = __floats2half2_rn(v.x, v.y);
            __half2 h1 = __floats2half2_rn(v.z, v.w);
            uint2 u;
            u.x = *reinterpret_cast<uint32_t*>(&h0);
            u.y = *reinterpret_cast<uint32_t*>(&h1);
            *reinterpret_cast<uint2*>(dst + SWZ(r * 128 + c4 * 2, r)) = u;
        }
    };
    auto fillB = [&](int k0, uint32_t dstu) {
        #pragma unroll
        for (int l = 0; l < 4; l++) {
            int f = tid + l * 256;
            int r = f >> 3, c8 = (f & 7) << 3;
            CP16(dstu + SWZ(r * 128 + c8 * 2, r),
                 Bt + (size_t)(col0 + r) * 384 + 128 + k0 + c8);
        }
    };

    const int t8 = lane >> 3, rr = lane & 7;
    const int a_row_l = (t8 & 1) * 8 + rr, a_k8 = (t8 >> 1) * 8;
    const int b_n_l   = (t8 >> 1) * 8 + rr, b_k8 = (t8 & 1) * 8;
    uint32_t sbase = smem_u32(smem);

    fillA(0, smem);
    fillB(0, sbase + 16384);
    CP_COMMIT();

    #pragma unroll
    for (int i = 0; i < 4; i++) {            // K = 256 -> 4 steps
        CP_WAIT0();
        __syncthreads();
        if (i + 1 < 4) {
            char* nb = smem + ((i + 1) & 1) * 32768;
            fillA((i + 1) << 6, nb);
            fillB((i + 1) << 6, sbase + ((i + 1) & 1) * 32768 + 16384);
            CP_COMMIT();
        }
        uint32_t smA = sbase + (i & 1) * 32768;
        uint32_t smB = smA + 16384;

        #pragma unroll
        for (int kk = 0; kk < 64; kk += 16) {
            uint32_t a[4][4], b[4][2];
            #pragma unroll
            for (int ma = 0; ma < 4; ma++) {
                int row = wm + ma * 16 + a_row_l;
                ldm_x4(a[ma], smA + SWZ(row * 128 + (kk + a_k8) * 2, row));
            }
            #pragma unroll
            for (int p = 0; p < 2; p++) {
                int n = wn + p * 16 + b_n_l;
                uint32_t r4[4];
                ldm_x4(r4, smB + SWZ(n * 128 + (kk + b_k8) * 2, n));
                b[p * 2 + 0][0] = r4[0]; b[p * 2 + 0][1] = r4[1];
                b[p * 2 + 1][0] = r4[2]; b[p * 2 + 1][1] = r4[3];
            }
            #pragma unroll
            for (int ma = 0; ma < 4; ma++)
                #pragma unroll
                for (int na = 0; na < 4; na++)
                    mma_f16(acc[ma][na], a[ma], b[na]);
        }
    }

    #pragma unroll
    for (int ma = 0; ma < 4; ma++) {
        int rlo = row0 + wm + ma * 16 + quad;
        int rhi = rlo + 8;
        #pragma unroll
        for (int na = 0; na < 4; na++) {
            int col = col0 + wn + na * 8 + 2 * tq;
            float2 s0, s1;
            s0.x = acc[ma][na][0]; s0.y = acc[ma][na][1];
            s1.x = acc[ma][na][2]; s1.y = acc[ma][na][3];
            *reinterpret_cast<float2*>(Cf + (size_t)rlo * 256 + col) = s0;
            *reinterpret_cast<float2*>(Cf + (size_t)rhi * 256 + col) = s1;
        }
    }
}

// ---------------------------------------------------------------------------
// Fused layers 1+2. CTA = 128 rows x full 256 cols, 512 threads (4m x 4n
// warps, warp tile 32x64). Phase 1: H = relu(fea1@W1a + gather(G2) + b1),
// fp16 H kept in SMEM (4 swizzled A-tile chunks). Phase 2: out =
// relu(H@W2 + b2), W2 streamed via cp.async.
// SMEM overlay (128 KB): [0,32K) A bufs / W2 bufs lo, [32K,96K) B1 bufs /
// W2 buf hi + H lo, [64K,128K) H chunks. Phase barriers make overlays safe.
// ---------------------------------------------------------------------------
#define FUSED_SMEM 131072

__global__ __launch_bounds__(512, 1) void fused_mlp(
    const float* __restrict__ fea1, const __half* __restrict__ Wt1,
    const __half* __restrict__ Wt2, float* __restrict__ out,
    const float* __restrict__ b1, const float* __restrict__ b2,
    const float* __restrict__ G2, const int* __restrict__ idx,
    const float* __restrict__ wts)
{
    extern __shared__ __align__(1024) char smem[];
    uint32_t sbase = smem_u32(smem);
    const int tid  = threadIdx.x;
    const int lane = tid & 31, w = tid >> 5;
    const int wm   = (w >> 2) << 5;     // 0,32,64,96
    const int wn   = (w & 3) << 6;      // 0,64,128,192
    const int quad = lane >> 2, tq = lane & 3;
    const int row0 = blockIdx.x << 7;

    const int t8 = lane >> 3, rr = lane & 7;
    const int a_row_l = (t8 & 1) * 8 + rr, a_k8 = (t8 >> 1) * 8;
    const int b_n_l   = (t8 >> 1) * 8 + rr, b_k8 = (t8 & 1) * 8;

    const uint32_t SH = sbase + 65536;  // H chunks: 4 x 16 KB

    float acc[2][8][4];
    #pragma unroll
    for (int ma = 0; ma < 2; ma++)
        #pragma unroll
        for (int na = 0; na < 8; na++)
            #pragma unroll
            for (int q = 0; q < 4; q++) acc[ma][na][q] = 0.0f;

    // --- fills ---
    auto fillA = [&](int k0, char* dst) {          // fea1 fp32 -> fp16, 128x64
        #pragma unroll
        for (int l = 0; l < 4; l++) {
            int f = tid + l * 512;
            int r = f >> 4, c4 = (f & 15) << 2;
            float4 v = *reinterpret_cast<const float4*>(
                fea1 + (size_t)(row0 + r) * C1 + k0 + c4);
            __half2 h0 = __floats2half2_rn(v.x, v.y);
            __half2 h1 = __floats2half2_rn(v.z, v.w);
            uint2 u;
            u.x = *reinterpret_cast<uint32_t*>(&h0);
            u.y = *reinterpret_cast<uint32_t*>(&h1);
            *reinterpret_cast<uint2*>(dst + SWZ(r * 128 + c4 * 2, r)) = u;
        }
    };
    auto cpB1 = [&](int k0, uint32_t dstu) {       // W1t rows 0..255, 256x64
        #pragma unroll
        for (int l = 0; l < 4; l++) {
            int f = tid + l * 512;
            int r = f >> 3, c8 = (f & 7) << 3;
            CP16(dstu + SWZ(r * 128 + c8 * 2, r),
                 Wt1 + (size_t)r * 384 + k0 + c8);
        }
    };
    auto cpW2 = [&](int s, uint32_t dstu) {        // W2t 256 x 64 chunk s
        #pragma unroll
        for (int l = 0; l < 4; l++) {
            int f = tid + l * 512;
            int r = f >> 3, c8 = (f & 7) << 3;
            CP16(dstu + SWZ(r * 128 + c8 * 2, r),
                 Wt2 + (size_t)r * 256 + s * 64 + c8);
        }
    };

    auto compute_step = [&](uint32_t smA, uint32_t smB) {
        #pragma unroll
        for (int kk = 0; kk < 64; kk += 16) {
            uint32_t a[2][4], b[8][2];
            #pragma unroll
            for (int ma = 0; ma < 2; ma++) {
                int row = wm + ma * 16 + a_row_l;
                ldm_x4(a[ma], smA + SWZ(row * 128 + (kk + a_k8) * 2, row));
            }
            #pragma unroll
            for (int p = 0; p < 4; p++) {
                int n = wn + p * 16 + b_n_l;
                uint32_t r4[4];
                ldm_x4(r4, smB + SWZ(n * 128 + (kk + b_k8) * 2, n));
                b[p * 2 + 0][0] = r4[0]; b[p * 2 + 0][1] = r4[1];
                b[p * 2 + 1][0] = r4[2]; b[p * 2 + 1][1] = r4[3];
            }
            #pragma unroll
            for (int ma = 0; ma < 2; ma++)
                #pragma unroll
                for (int na = 0; na < 8; na++)
                    mma_f16(acc[ma][na], a[ma], b[na]);
        }
    };

    // ===== Phase 1: layer 1, K=128, 2 steps of 64 =====
    fillA(0, smem);
    cpB1(0, sbase + 32768);
    CP_COMMIT();

    #pragma unroll
    for (int i = 0; i < 2; i++) {
        CP_WAIT0();
        __syncthreads();
        if (i == 0) {
            fillA(64, smem + 16384);
            cpB1(64, sbase + 32768 + 32768);
            CP_COMMIT();
        }
        compute_step(sbase + i * 16384, sbase + 32768 + i * 32768);
    }
    __syncthreads();                 // all phase-1 smem reads done

    // start streaming W2 chunk 0 into [0,32K) (old A bufs)
    cpW2(0, sbase);
    CP_COMMIT();

    // ---- Phase-1 epilogue: gather + bias + relu -> fp16 H in SMEM ----
    int colb[8];
    #pragma unroll
    for (int na = 0; na < 8; na++) colb[na] = wn + na * 8 + 2 * tq;

    #pragma unroll
    for (int ma = 0; ma < 2; ma++) {
        #pragma unroll
        for (int h = 0; h < 2; h++) {
            int lr = wm + ma * 16 + quad + h * 8;     // CTA-local row
            int gr = row0 + lr;
            int bb = gr >> 12;
            const int*   ip = idx + (size_t)gr * 3;
            const float* wp = wts + (size_t)gr * 3;
            #pragma unroll
            for (int k = 0; k < 3; k++) {
                int   ii = ip[k];
                float wt = wp[k];
                const float* g = G2 + (size_t)((bb << 10) + ii) * CH;
                #pragma unroll
                for (int na = 0; na < 8; na++) {
                    float2 u = *reinterpret_cast<const float2*>(g + colb[na]);
                    acc[ma][na][2 * h + 0] = fmaf(wt, u.x, acc[ma][na][2 * h + 0]);
                    acc[ma][na][2 * h + 1] = fmaf(wt, u.y, acc[ma][na][2 * h + 1]);
                }
            }
        }
    }
    #pragma unroll
    for (int na = 0; na < 8; na++) {
        float2 bv = *reinterpret_cast<const float2*>(b1 + colb[na]);
        #pragma unroll
        for (int ma = 0; ma < 2; ma++) {
            acc[ma][na][0] = fmaxf(acc[ma][na][0] + bv.x, 0.0f);
            acc[ma][na][1] = fmaxf(acc[ma][na][1] + bv.y, 0.0f);
            acc[ma][na][2] = fmaxf(acc[ma][na][2] + bv.x, 0.0f);
            acc[ma][na][3] = fmaxf(acc[ma][na][3] + bv.y, 0.0f);
        }
    }
    // store H tile (fp16, swizzled A-tile layout, 4 chunks of 64 cols)
    #pragma unroll
    for (int ma = 0; ma < 2; ma++) {
        int rlo = wm + ma * 16 + quad;
        int rhi = rlo + 8;
        #pragma unroll
        for (int na = 0; na < 8; na++) {
            int col = colb[na];
            uint32_t ch = SH + (col >> 6) * 16384;
            int cw2 = (col & 63) * 2;
            __half2 s0 = __floats2half2_rn(acc[ma][na][0], acc[ma][na][1]);
            __half2 s1 = __floats2half2_rn(acc[ma][na][2], acc[ma][na][3]);
            *reinterpret_cast<__half2*>(smem + (ch - sbase) + SWZ(rlo * 128 + cw2, rlo)) = s0;
            *reinterpret_cast<__half2*>(smem + (ch - sbase) + SWZ(rhi * 128 + cw2, rhi)) = s1;
        }
    }

    // reset accumulators for layer 2
    #pragma unroll
    for (int ma = 0; ma < 2; ma++)
        #pragma unroll
        for (int na = 0; na < 8; na++)
            #pragma unroll
            for (int q = 0; q < 4; q++) acc[ma][na][q] = 0.0f;

    // ===== Phase 2: layer 2, K=256, 4 steps; A = H chunks (resident) =====
    #pragma unroll
    for (int s = 0; s < 4; s++) {
        CP_WAIT0();
        __syncthreads();
        if (s + 1 < 4) {
            cpW2(s + 1, sbase + ((s + 1) & 1) * 32768);
            CP_COMMIT();
        }
        compute_step(SH + s * 16384, sbase + (s & 1) * 32768);
    }

    // ---- Phase-2 epilogue: bias + relu -> fp32 out ----
    #pragma unroll
    for (int na = 0; na < 8; na++) {
        float2 bv = *reinterpret_cast<const float2*>(b2 + colb[na]);
        #pragma unroll
        for (int ma = 0; ma < 2; ma++) {
            acc[ma][na][0] = fmaxf(acc[ma][na][0] + bv.x, 0.0f);
            acc[ma][na][1] = fmaxf(acc[ma][na][1] + bv.y, 0.0f);
            acc[ma][na][2] = fmaxf(acc[ma][na][2] + bv.x, 0.0f);
            acc[ma][na][3] = fmaxf(acc[ma][na][3] + bv.y, 0.0f);
        }
    }
    #pragma unroll
    for (int ma = 0; ma < 2; ma++) {
        int rlo = row0 + wm + ma * 16 + quad;
        int rhi = rlo + 8;
        #pragma unroll
        for (int na = 0; na < 8; na++) {
            float2 s0, s1;
            s0.x = acc[ma][na][0]; s0.y = acc[ma][na][1];
            s1.x = acc[ma][na][2]; s1.y = acc[ma][na][3];
            *reinterpret_cast<float2*>(out + (size_t)rlo * 256 + colb[na]) = s0;
            *reinterpret_cast<float2*>(out + (size_t)rhi * 256 + colb[na]) = s1;
        }
    }
}

// ---------------------------------------------------------------------------

extern "C" void kernel_launch(void* const* d_in, const int* in_sizes, int n_in,
                              void* d_out, int out_size)
{
    const float* xyz1 = (const float*)d_in[0];
    const float* xyz2 = (const float*)d_in[1];
    const float* fea1 = (const float*)d_in[2];
    const float* fea2 = (const float*)d_in[3];
    const float* W1   = (const float*)d_in[4];
    const float* b1   = (const float*)d_in[5];
    const float* W2   = (const float*)d_in[6];
    const float* b2   = (const float*)d_in[7];
    float* out = (float*)d_out;

    void *p_idx, *p_wts, *p_G2, *p_Wt1, *p_Wt2;
    cudaGetSymbolAddress(&p_idx, g_idx);
    cudaGetSymbolAddress(&p_wts, g_wts);
    cudaGetSymbolAddress(&p_G2,  g_G2);
    cudaGetSymbolAddress(&p_Wt1, g_Wt1);
    cudaGetSymbolAddress(&p_Wt2, g_Wt2);
    int*    idxp = (int*)p_idx;
    float*  wtsp = (float*)p_wts;
    float*  G2p  = (float*)p_G2;
    __half* Wt1p = (__half*)p_Wt1;
    __half* Wt2p = (__half*)p_Wt2;

    cudaFuncSetAttribute(g2_gemm,   cudaFuncAttributeMaxDynamicSharedMemorySize, G2_SMEM);
    cudaFuncSetAttribute(fused_mlp, cudaFuncAttributeMaxDynamicSharedMemorySize, FUSED_SMEM);

    // 0) transpose + fp16-convert weights (tiny)
    transpose_w<<<(384 * 256 + 255) / 256, 256>>>(W1, Wt1p, 384);
    transpose_w<<<(256 * 256 + 255) / 256, 256>>>(W2, Wt2p, 256);

    // 1) 3-NN search + weights
    knn_kernel<<<dim3(N1 / 256, BS), 256>>>(xyz1, xyz2, idxp, wtsp);

    // 2) G2 = fea2 @ W1b
    g2_gemm<<<dim3(2, (BS * N2) / 128), 256, G2_SMEM>>>(fea2, Wt1p, G2p);

    // 3+4) fused: H = relu(fea1@W1a + gather(G2) + b1); out = relu(H@W2 + b2)
    fused_mlp<<<(BS * N1) / 128, 512, FUSED_SMEM>>>(
        fea1, Wt1p, Wt2p, out, b1, b2, G2p, idxp, wtsp);
}